// round 6
// baseline (speedup 1.0000x reference)
#include <cuda_runtime.h>
#include <math.h>

#define NT   512
#define BSUB 8
#define TT   128
#define DD   256
#define HW   128

__device__ __forceinline__ float tanha(float x) {
    float y; asm("tanh.approx.f32 %0, %1;" : "=f"(y) : "f"(x)); return y;
}
#define FFMA2(acc, a, b) \
    asm("fma.rn.f32x2 %0, %1, %2, %3;" : "=l"(acc) : "l"(a), "l"(b), "l"(acc))
#define PACK2(d, lo, hi) \
    asm("mov.b64 %0, {%1,%2};" : "=l"(d) : "f"(lo), "f"(hi))
#define UNPACK2(lo, hi, d) \
    asm("mov.b64 {%0,%1}, %2;" : "=f"(lo), "=f"(hi) : "l"(d))

__device__ __forceinline__ float interp_c(float t, const float* __restrict__ row) {
    int i = (int)ceilf(t);
    i = i < 1 ? 1 : (i > DD - 1 ? DD - 1 : i);
    float w = t - (float)(i - 1);
    w = fminf(fmaxf(w, 0.f), 1.f);
    return (1.f - w) * row[i - 1] + w * row[i];
}

__global__ __launch_bounds__(NT, 1)
void ode_kernel(const float* __restrict__ ts, const float* __restrict__ y0,
                const float* __restrict__ latent, const int* __restrict__ length,
                const float* __restrict__ dts, const float* __restrict__ dcs,
                const float* __restrict__ W1, const float* __restrict__ b1,
                const float* __restrict__ W2, const float* __restrict__ b2,
                const float* __restrict__ W3, const float* __restrict__ b3,
                float* __restrict__ out)
{
    extern __shared__ float sm[];
    float* W3t = sm;                // [128][9]
    float* h1s = W3t + 1152;        // [8][128]
    float* pS  = h1s + 1024;        // [2][8][128]
    float* csS = pS + 2048;         // [8][256]
    float* tsS = csS + 2048;        // [128]
    float* b2s = tsS + 128;         // [128]
    float* b3s = b2s + 128;         // [12]

    const int tid = threadIdx.x;
    const int wid = tid >> 5;
    const int l   = tid & 31;
    const bool isRow = (wid < 8);
    const int r0  = blockIdx.x * BSUB;

    // ---- common smem setup ----
    for (int i = tid; i < 9 * HW; i += NT) {
        int oo = i >> 7, k = i & 127;
        W3t[k * 9 + oo] = W3[i];
    }
    for (int i = tid; i < BSUB * DD; i += NT) {
        int r = i >> 8;
        csS[i] = dcs[(r0 + r) * DD + (i & 255)];
    }
    if (tid < TT) tsS[tid] = ts[tid];
    if (tid >= 128 && tid < 256) b2s[tid - 128] = b2[tid - 128];
    if (tid >= 256 && tid < 265) b3s[tid - 256] = b3[tid - 256];

    // ---- role-specific register state (shared physical array) ----
    // GEMM warps: u[0..31]  = W2[o][64e .. 64e+63] packed f32x2
    // Row warps:  u[0..19]  = w1 (4 neurons x 5 pairs, y-padded)
    //             u[20..23] = (w1_t, w1_c) per neuron
    //             u[24..27] = (bpre, 0)   per neuron
    //             u[28..32] = Ybase (9 states packed, pad 0)
    //             u[33..37] = Yacc
    unsigned long long u[38];
    float tend = 0.f;

    if (!isRow) {
        int w = wid - 8;
        int o = 32 * (w & 3) + l;
        int e = w >> 2;
        const float* wr = W2 + o * HW + 64 * e;
        #pragma unroll
        for (int j = 0; j < 32; ++j) PACK2(u[j], wr[2 * j], wr[2 * j + 1]);
    } else {
        const int r = wid;
        const float* lat = latent + (r0 + r) * 32;
        #pragma unroll
        for (int nn = 0; nn < 4; ++nn) {
            const int o = 4 * l + nn;
            const float* w = W1 + o * 43;
            PACK2(u[nn * 5 + 0], w[0], w[1]);
            PACK2(u[nn * 5 + 1], w[2], w[3]);
            PACK2(u[nn * 5 + 2], w[4], w[5]);
            PACK2(u[nn * 5 + 3], w[6], w[7]);
            PACK2(u[nn * 5 + 4], w[8], 0.f);
            PACK2(u[20 + nn], w[41], w[42]);
            float bp = b1[o];
            #pragma unroll
            for (int j = 0; j < 32; ++j) bp += w[9 + j] * lat[j];
            PACK2(u[24 + nn], bp, 0.f);
        }
        float y0r = y0[r0 + r];
        PACK2(u[28], y0r, 0.f);
        PACK2(u[29], 0.f, 0.f); u[30] = u[29]; u[31] = u[29]; u[32] = u[29];
        #pragma unroll
        for (int jj = 0; jj < 5; ++jj) u[33 + jj] = u[28 + jj];
        int len = length[r0 + r];
        int idx = len - 1; if (idx < 0) idx = 0;
        tend = ts[idx];
        if (l == 0) out[(r0 + r) * TT] = y0r;
    }
    __syncthreads();

    #pragma unroll 1
    for (int n = 0; n < TT - 1; ++n) {
        float t0  = tsS[n];
        float dtf = (tsS[n + 1] - t0) * 0.5f;           // SUB = 2
        #pragma unroll 1
        for (int sub = 0; sub < 2; ++sub) {
            float tstart = t0 + (float)sub * dtf;
            unsigned long long y2[5];
            float c_cur = 0.f;
            if (isRow) {
                #pragma unroll
                for (int jj = 0; jj < 5; ++jj) y2[jj] = u[28 + jj];
                c_cur = interp_c(tstart, csS + wid * DD);
            }
            #pragma unroll 1
            for (int s = 0; s < 4; ++s) {
                float aS = (s == 0) ? 0.f : ((s == 3) ? 1.f : 0.5f);
                float tt = tstart + aS * dtf;

                if (isRow) {
                    // ---- layer 1 (row warp r = wid; lane does neurons 4l..4l+3) ----
                    unsigned long long tc2; PACK2(tc2, tt, c_cur);
                    float h[4];
                    #pragma unroll
                    for (int nn = 0; nn < 4; ++nn) {
                        unsigned long long a2 = u[24 + nn];
                        FFMA2(a2, u[nn * 5 + 0], y2[0]);
                        FFMA2(a2, u[nn * 5 + 1], y2[1]);
                        FFMA2(a2, u[nn * 5 + 2], y2[2]);
                        FFMA2(a2, u[nn * 5 + 3], y2[3]);
                        FFMA2(a2, u[nn * 5 + 4], y2[4]);
                        FFMA2(a2, u[20 + nn], tc2);
                        float lo, hi; UNPACK2(lo, hi, a2);
                        h[nn] = tanha(lo + hi);
                    }
                    float4 hv4 = make_float4(h[0], h[1], h[2], h[3]);
                    *reinterpret_cast<float4*>(h1s + wid * HW + 4 * l) = hv4;
                }
                __syncthreads();

                if (!isRow) {
                    // ---- layer 2 (GEMM warps): 8 rows x 64 k, W2 in regs ----
                    int w = wid - 8;
                    int o = 32 * (w & 3) + l;
                    int e = w >> 2;
                    unsigned long long acc[BSUB];
                    #pragma unroll
                    for (int rr = 0; rr < BSUB; ++rr) acc[rr] = 0ull;
                    const float* hb = h1s + 64 * e;
                    #pragma unroll 4
                    for (int j = 0; j < 16; ++j) {
                        #pragma unroll
                        for (int rr = 0; rr < BSUB; ++rr) {
                            ulonglong2 hv = *reinterpret_cast<const ulonglong2*>(hb + rr * HW + 4 * j);
                            FFMA2(acc[rr], u[2 * j],     hv.x);
                            FFMA2(acc[rr], u[2 * j + 1], hv.y);
                        }
                    }
                    float* pq = pS + e * (BSUB * HW) + o;
                    #pragma unroll
                    for (int rr = 0; rr < BSUB; ++rr) {
                        float lo, hi; UNPACK2(lo, hi, acc[rr]);
                        pq[rr * HW] = lo + hi;
                    }
                }
                __syncthreads();

                if (isRow) {
                    // ---- layer 3 + RK4 epilogue (all in registers) ----
                    const int r = wid;
                    float acc9[9];
                    #pragma unroll
                    for (int o2 = 0; o2 < 9; ++o2) acc9[o2] = 0.f;
                    const float* pr = pS + r * HW;
                    #pragma unroll
                    for (int j = 0; j < 4; ++j) {
                        int k = 32 * j + l;
                        float v = pr[k] + pr[BSUB * HW + k] + b2s[k];
                        float hh = tanha(v);
                        #pragma unroll
                        for (int o2 = 0; o2 < 9; ++o2)
                            acc9[o2] += hh * W3t[k * 9 + o2];
                    }
                    #pragma unroll
                    for (int off = 16; off > 0; off >>= 1) {
                        #pragma unroll
                        for (int o2 = 0; o2 < 9; ++o2)
                            acc9[o2] += __shfl_xor_sync(0xffffffffu, acc9[o2], off);
                    }
                    // epilogue — every lane has full sums; all-lane replicated
                    float wS  = (s == 0 || s == 3) ? 1.f : 2.f;
                    float wgt = dtf * (1.f / 6.f) * wS;
                    bool stop = (tt > tend);
                    float kv[10];
                    #pragma unroll
                    for (int o2 = 0; o2 < 9; ++o2) {
                        float a = acc9[o2] + b3s[o2];
                        if (o2 == 0) a = -__cosf(a);
                        kv[o2] = stop ? 0.f : a;
                    }
                    kv[9] = 0.f;
                    unsigned long long wg2; PACK2(wg2, wgt, wgt);
                    float stg = ((s == 2) ? 1.f : 0.5f) * dtf;
                    unsigned long long s2; PACK2(s2, stg, stg);
                    #pragma unroll
                    for (int jj = 0; jj < 5; ++jj) {
                        unsigned long long k2; PACK2(k2, kv[2 * jj], kv[2 * jj + 1]);
                        FFMA2(u[33 + jj], wg2, k2);         // Yacc += wgt * k
                        if (s < 3) {
                            unsigned long long t2 = u[28 + jj];
                            FFMA2(t2, s2, k2);              // Ystage = Ybase + stg * k
                            y2[jj] = t2;
                        }
                    }
                    if (s < 3)
                        c_cur = interp_c(tstart + ((s == 2) ? 1.f : 0.5f) * dtf, csS + r * DD);
                }
            } // s

            if (isRow) {
                #pragma unroll
                for (int jj = 0; jj < 5; ++jj) u[28 + jj] = u[33 + jj];  // commit
            }
        } // sub

        if (isRow && l == 0) {
            float yb, dummy; UNPACK2(yb, dummy, u[28]);
            out[(r0 + wid) * TT + n + 1] = yb;
        }
    }
}

extern "C" void kernel_launch(void* const* d_in, const int* in_sizes, int n_in,
                              void* d_out, int out_size) {
    const float* ts     = (const float*)d_in[0];
    const float* y0     = (const float*)d_in[1];
    const float* latent = (const float*)d_in[2];
    const int*   length = (const int*)  d_in[3];
    const float* dts    = (const float*)d_in[4];
    const float* dcs    = (const float*)d_in[5];
    const float* W1     = (const float*)d_in[6];
    const float* b1     = (const float*)d_in[7];
    const float* W2     = (const float*)d_in[8];
    const float* b2     = (const float*)d_in[9];
    const float* W3     = (const float*)d_in[10];
    const float* b3     = (const float*)d_in[11];
    float* out = (float*)d_out;

    const size_t smem_floats = 1152 + 1024 + 2048 + 2048 + 128 + 128 + 12;
    const size_t smem = smem_floats * sizeof(float);   // 26160 B
    cudaFuncSetAttribute(ode_kernel, cudaFuncAttributeMaxDynamicSharedMemorySize, (int)smem);

    ode_kernel<<<128, NT, smem>>>(ts, y0, latent, length, dts, dcs,
                                  W1, b1, W2, b2, W3, b3, out);
}

// round 7
// speedup vs baseline: 1.8965x; 1.8965x over previous
#include <cuda_runtime.h>
#include <math.h>

#define NT   256   // 8 warps; L2 thread = (og 0..31, kg 0..7)
#define BSUB 4     // batch rows per CTA
#define TT   128
#define DD   256
#define HW   128
#define HTS  12    // h1t stride in floats (48B: 16B-aligned for every k)

__device__ __forceinline__ float tanha(float x) {
    float y; asm("tanh.approx.f32 %0, %1;" : "=f"(y) : "f"(x)); return y;
}
#define FFMA2(acc, a, b) \
    asm("fma.rn.f32x2 %0, %1, %2, %3;" : "=l"(acc) : "l"(a), "l"(b), "l"(acc))
#define PACK2(d, lo, hi) \
    asm("mov.b64 %0, {%1,%2};" : "=l"(d) : "f"(lo), "f"(hi))
#define UNPACK2(lo, hi, d) \
    asm("mov.b64 {%0,%1}, %2;" : "=f"(lo), "=f"(hi) : "l"(d))

__device__ __forceinline__ float interp_c(float t, const float* __restrict__ row) {
    int i = (int)ceilf(t);
    i = i < 1 ? 1 : (i > DD - 1 ? DD - 1 : i);
    float w = t - (float)(i - 1);
    w = fminf(fmaxf(w, 0.f), 1.f);
    return (1.f - w) * row[i - 1] + w * row[i];
}

__global__ __launch_bounds__(NT, 2)
void ode_kernel(const float* __restrict__ ts, const float* __restrict__ y0,
                const float* __restrict__ latent, const int* __restrict__ length,
                const float* __restrict__ dts, const float* __restrict__ dcs,
                const float* __restrict__ W1, const float* __restrict__ b1,
                const float* __restrict__ W2, const float* __restrict__ b2,
                const float* __restrict__ W3, const float* __restrict__ b3,
                float* __restrict__ out)
{
    extern __shared__ float sm[];
    float* W3t    = sm;                   // [128][9]
    float* h1t    = W3t + 1152;           // [128][12]  h1t[k][r], r<4
    float* pSf    = h1t + HW * HTS;       // pS_u64[rp][kg][o] = 2*8*128 u64 = 4096 f
    float* bpre   = pSf + 4096;           // [4][128]
    float* csS    = bpre + BSUB * HW;     // [4][256]
    float* tsS    = csS + BSUB * DD;      // [128]
    float* b2s    = tsS + TT;             // [128]
    float* Ybase  = b2s + HW;             // [4][12]
    float* Ystage = Ybase + BSUB * 12;    // [4][12]
    float* Yacc   = Ystage + BSUB * 12;   // [4][12]
    float* cS     = Yacc + BSUB * 12;     // [4]
    float* b3s    = cS + 4;               // [12]
    float* tendS  = b3s + 12;             // [4]
    unsigned long long* pS = reinterpret_cast<unsigned long long*>(pSf);

    const int tid = threadIdx.x;
    const int og  = tid & 31;             // lane
    const int kg  = tid >> 5;             // warp 0..7 (k-group: k = 16kg..16kg+15)
    const int r0  = blockIdx.x * BSUB;

    // L1 mapping: this thread computes neuron o1 for rows 2e, 2e+1
    const int o1 = og + 32 * (kg & 3);
    const int e  = kg >> 2;

    // ---- one-time setup ----
    for (int i = tid; i < 9 * HW; i += NT) {
        int oo = i >> 7, k = i & 127;
        W3t[k * 9 + oo] = W3[i];
    }
    for (int i = tid; i < BSUB * DD; i += NT) {
        int r = i >> 8;
        csS[i] = dcs[(r0 + r) * DD + (i & 255)];
    }
    if (tid < TT) tsS[tid] = ts[tid];
    if (tid >= 128) b2s[tid - 128] = b2[tid - 128];
    if (tid < 9)  b3s[tid] = b3[tid];
    if (tid >= 16 && tid < 16 + BSUB) {
        int r = tid - 16;
        int len = length[r0 + r];
        int idx = len - 1; if (idx < 0) idx = 0;
        tendS[r] = ts[idx];
        out[(r0 + r) * TT] = y0[r0 + r];
    }
    if (tid >= 32 && tid < 32 + BSUB * 12) {
        int i = tid - 32;
        int r = i / 12, j = i - r * 12;
        float v = (j == 0) ? y0[r0 + r] : 0.f;
        Ybase[i] = v;
        Yacc[i]  = v;
    }

    // ---- register-resident weights ----
    // L2: W2 rows o = og + 32m, k = 16kg..16kg+15  (64 scalar regs)
    float w2s[4][16];
    #pragma unroll
    for (int m = 0; m < 4; ++m) {
        const float* wr = W2 + (og + 32 * m) * HW + 16 * kg;
        #pragma unroll
        for (int kk = 0; kk < 16; ++kk) w2s[m][kk] = wr[kk];
    }
    // L1 weights for neuron o1 (packed)
    unsigned long long w1p[5];
    float w1t, w1c;
    {
        const float* w = W1 + o1 * 43;
        PACK2(w1p[0], w[0], w[1]);
        PACK2(w1p[1], w[2], w[3]);
        PACK2(w1p[2], w[4], w[5]);
        PACK2(w1p[3], w[6], w[7]);
        PACK2(w1p[4], w[8], 0.f);
        w1t = w[41];
        w1c = w[42];
        float bb = b1[o1];
        #pragma unroll
        for (int rr = 0; rr < 2; ++rr) {          // rows 2e, 2e+1
            int r = 2 * e + rr;
            float a = bb;
            const float* lat = latent + (r0 + r) * 32;
            #pragma unroll
            for (int j = 0; j < 32; ++j) a += w[9 + j] * lat[j];
            bpre[r * HW + o1] = a;
        }
    }
    __syncthreads();

    const float A[4]  = {0.f, 0.5f, 0.5f, 1.f};
    const float Wc[4] = {1.f, 2.f, 2.f, 1.f};
    const int l = og;                      // lane within warp

    for (int n = 0; n < TT - 1; ++n) {
        float t0  = tsS[n];
        float dtf = (tsS[n + 1] - t0) * 0.5f;     // SUB = 2
        #pragma unroll 1
        for (int sub = 0; sub < 2; ++sub) {
            float tstart = t0 + (float)sub * dtf;
            if (tid < BSUB * 12) Ystage[tid] = Ybase[tid];
            if (tid >= 64 && tid < 64 + BSUB)
                cS[tid - 64] = interp_c(tstart, csS + (tid - 64) * DD);
            __syncthreads();

            #pragma unroll
            for (int s = 0; s < 4; ++s) {
                float tt  = tstart + A[s] * dtf;
                float wgt = dtf * (1.f / 6.f) * Wc[s];

                // ---- layer 1: neuron o1, rows 2e,2e+1; store transposed ----
                {
                    float h2v[2];
                    #pragma unroll
                    for (int rr = 0; rr < 2; ++rr) {
                        const int r = 2 * e + rr;
                        float base = bpre[r * HW + o1] + w1t * tt + w1c * cS[r];
                        ulonglong2 ya = *reinterpret_cast<const ulonglong2*>(Ystage + r * 12);
                        ulonglong2 yb = *reinterpret_cast<const ulonglong2*>(Ystage + r * 12 + 4);
                        unsigned long long y8p;
                        PACK2(y8p, Ystage[r * 12 + 8], 0.f);
                        unsigned long long a2 = 0ull;
                        FFMA2(a2, w1p[0], ya.x);
                        FFMA2(a2, w1p[1], ya.y);
                        FFMA2(a2, w1p[2], yb.x);
                        FFMA2(a2, w1p[3], yb.y);
                        FFMA2(a2, w1p[4], y8p);
                        float lo, hi; UNPACK2(lo, hi, a2);
                        h2v[rr] = tanha(base + lo + hi);
                    }
                    unsigned long long hp; PACK2(hp, h2v[0], h2v[1]);
                    *reinterpret_cast<unsigned long long*>(h1t + o1 * HTS + 2 * e) = hp;
                }
                __syncthreads();

                // ---- layer 2: 4 o x 16 k x 4 rows register tile ----
                {
                    unsigned long long acc[4][2];
                    #pragma unroll
                    for (int m = 0; m < 4; ++m) { acc[m][0] = 0ull; acc[m][1] = 0ull; }
                    const float* hk = h1t + 16 * kg * HTS;
                    #pragma unroll 4
                    for (int kk = 0; kk < 16; ++kk) {
                        ulonglong2 hv = *reinterpret_cast<const ulonglong2*>(hk + kk * HTS);
                        #pragma unroll
                        for (int m = 0; m < 4; ++m) {
                            unsigned long long wrep;
                            PACK2(wrep, w2s[m][kk], w2s[m][kk]);
                            FFMA2(acc[m][0], wrep, hv.x);
                            FFMA2(acc[m][1], wrep, hv.y);
                        }
                    }
                    // pS_u64[rp][kg][o] — conflict-free (o = og+32m)
                    #pragma unroll
                    for (int m = 0; m < 4; ++m) {
                        int o = og + 32 * m;
                        pS[kg * 128 + o]        = acc[m][0];
                        pS[1024 + kg * 128 + o] = acc[m][1];
                    }
                }
                __syncthreads();

                // ---- layer 3: warp-per-row (warps 0-3); fold pS-reduce + tanh ----
                if (kg < BSUB) {
                    const int r = kg;
                    const int rp = r >> 1, rh = r & 1;
                    float acc9[9];
                    #pragma unroll
                    for (int o2 = 0; o2 < 9; ++o2) acc9[o2] = 0.f;
                    const float* pbase = pSf + rp * 2048 + rh;   // scalar halves of u64
                    #pragma unroll
                    for (int j = 0; j < 4; ++j) {
                        int k = 32 * j + l;
                        float v = b2s[k];
                        #pragma unroll
                        for (int g = 0; g < 8; ++g)
                            v += pbase[g * 256 + 2 * k];
                        float hh = tanha(v);
                        #pragma unroll
                        for (int o2 = 0; o2 < 9; ++o2)
                            acc9[o2] += hh * W3t[k * 9 + o2];
                    }
                    #pragma unroll
                    for (int off = 16; off > 0; off >>= 1) {
                        #pragma unroll
                        for (int o2 = 0; o2 < 9; ++o2)
                            acc9[o2] += __shfl_xor_sync(0xffffffffu, acc9[o2], off);
                    }
                    if (l < 9) {
                        float a = acc9[l] + b3s[l];
                        if (l == 0) a = -__cosf(a);
                        if (tt > tendS[r]) a = 0.f;
                        Yacc[r * 12 + l] += wgt * a;
                        if (s < 3)
                            Ystage[r * 12 + l] = Ybase[r * 12 + l] + (A[s + 1] * dtf) * a;
                    }
                    if (l == 16 && s < 3)
                        cS[r] = interp_c(tstart + A[s + 1] * dtf, csS + r * DD);
                }
                __syncthreads();
            }

            if (tid < BSUB * 12) Ybase[tid] = Yacc[tid];
            __syncthreads();
        }
        if (tid < BSUB) out[(r0 + tid) * TT + n + 1] = Ybase[tid * 12];
    }
}

extern "C" void kernel_launch(void* const* d_in, const int* in_sizes, int n_in,
                              void* d_out, int out_size) {
    const float* ts     = (const float*)d_in[0];
    const float* y0     = (const float*)d_in[1];
    const float* latent = (const float*)d_in[2];
    const int*   length = (const int*)  d_in[3];
    const float* dts    = (const float*)d_in[4];
    const float* dcs    = (const float*)d_in[5];
    const float* W1     = (const float*)d_in[6];
    const float* b1     = (const float*)d_in[7];
    const float* W2     = (const float*)d_in[8];
    const float* b2     = (const float*)d_in[9];
    const float* W3     = (const float*)d_in[10];
    const float* b3     = (const float*)d_in[11];
    float* out = (float*)d_out;

    const size_t smem_floats = 1152 + HW * HTS + 4096 + BSUB * HW
                             + BSUB * DD + TT + HW + 3 * BSUB * 12 + 4 + 12 + 4;
    const size_t smem = smem_floats * sizeof(float);   // ~34 KB per CTA
    cudaFuncSetAttribute(ode_kernel, cudaFuncAttributeMaxDynamicSharedMemorySize, (int)smem);

    ode_kernel<<<256, NT, smem>>>(ts, y0, latent, length, dts, dcs,
                                  W1, b1, W2, b2, W3, b3, out);
}